// round 15
// baseline (speedup 1.0000x reference)
#include <cuda_runtime.h>
#include <cuda_fp16.h>
#include <cstdint>

// Problem constants
#define BB 8
#define HH 128
#define WW 128
#define CC 16
#define HID 256
#define STEPS 16
#define NELEM (BB*HH*WW*CC)   // 2,097,152
#define NT 512

// SMEM layout (32-bit words). CTA tile: 8 y-rows x 16 x-cols = 128 cells (M=128).
#define OFF_HALO 0            // fp32 halo, channel-major: 16ch * 10y * 18x = 2880
#define OFF_CW   2880         // fp32 transposed conv w: [ci*9+rs][16 o] = 2304
#define OFF_P    5184         // P frags (f16 packed): 8mt * 32lane * 4 u32 = 1024
#define OFF_WFL  6208         // w_first (2048 u32) + w_last (2048 u32) = 4096
#define OFF_ACT  10304        // acts: 8mt * 16ktile * 32lane * 4 u32 = 16384
#define OFF_WBUF 26688        // 4-slot panel ring: 4 * 4096 u32 = 16384
#define SMEM_WORDS 43072
#define SMEM_BYTES (SMEM_WORDS*4)   // 172,288 B

// Pre-swizzled fp16-packed weights (u32 = 2 f16), written once per launch.
// interim: 24 panels (l*8+p) * 4096; u32 idx in panel = ((nt*2+kt)*32+lane)*2+b
//          n = nt*8+(lane>>2), k = p*32 + kt*16 + 2*(lane&3) + 8*b  (pair k,k+1)
#define WU_FIRST 98304
#define WU_LAST  100352
__device__ uint32_t g_wswz[102400];

__device__ __forceinline__ uint32_t packh(float lo, float hi) {
    uint32_t u;
    asm("cvt.rn.f16x2.f32 %0, %1, %2;" : "=r"(u) : "f"(hi), "f"(lo));
    return u;
}

// f16 inputs, f32 accumulators (first/last layers)
__device__ __forceinline__ void mmah32(float* c, const uint4& a, const uint2& b) {
    asm volatile(
        "mma.sync.aligned.m16n8k16.row.col.f32.f16.f16.f32 "
        "{%0,%1,%2,%3}, {%4,%5,%6,%7}, {%8,%9}, {%0,%1,%2,%3};\n"
        : "+f"(c[0]), "+f"(c[1]), "+f"(c[2]), "+f"(c[3])
        : "r"(a.x), "r"(a.y), "r"(a.z), "r"(a.w), "r"(b.x), "r"(b.y));
}

// f16 inputs, f16 accumulators (interim layers; promoted to f32 each k16)
__device__ __forceinline__ void mmah16(uint32_t& c0, uint32_t& c1, const uint4& a, const uint2& b) {
    asm volatile(
        "mma.sync.aligned.m16n8k16.row.col.f16.f16.f16.f16 "
        "{%0,%1}, {%2,%3,%4,%5}, {%6,%7}, {%0,%1};\n"
        : "+r"(c0), "+r"(c1)
        : "r"(a.x), "r"(a.y), "r"(a.z), "r"(a.w), "r"(b.x), "r"(b.y));
}

__device__ __forceinline__ void cpa16(uint32_t dst, const void* src) {
    asm volatile("cp.async.cg.shared.global [%0], [%1], 16;\n" :: "r"(dst), "l"(src));
}
__device__ __forceinline__ void cpa_commit() { asm volatile("cp.async.commit_group;\n" ::: "memory"); }
__device__ __forceinline__ void cpa_wait2()  { asm volatile("cp.async.wait_group 2;\n"  ::: "memory"); }

// ---------------- Pre-swizzle weights into packed-f16 mma fragment order -------------
__global__ void preswizzle_kernel(const float* __restrict__ wi,
                                  const float* __restrict__ wf,
                                  const float* __restrict__ wl)
{
    int idx = blockIdx.x * blockDim.x + threadIdx.x;
    if (idx >= 102400) return;
    float f0, f1;
    if (idx < WU_FIRST) {
        // ((((l*8+p)*32+nt)*2+kt)*32+lane)*2 + b
        int lane = (idx >> 1) & 31, kt = (idx >> 6) & 1, nt = (idx >> 7) & 31;
        int p = (idx >> 12) & 7, l = idx >> 15;
        int g = lane >> 2, t = lane & 3;
        int n = nt * 8 + g;
        int k = p * 32 + kt * 16 + 2 * t + 8 * (idx & 1);
        const float* row = wi + (l * HID + n) * HID;
        f0 = row[k]; f1 = row[k + 1];
    } else if (idx < WU_LAST) {
        int j = idx - WU_FIRST;          // (nt*32+lane)*2 + b
        int lane = (j >> 1) & 31, nt = (j >> 6) & 31;
        int g = lane >> 2, t = lane & 3;
        int n = nt * 8 + g;
        int k = 2 * t + 8 * (j & 1);
        f0 = wf[n * CC + k]; f1 = wf[n * CC + k + 1];
    } else {
        int j = idx - WU_LAST;           // ((kap*2+ntl)*32+lane)*2 + b
        int lane = (j >> 1) & 31, ntl = (j >> 6) & 1, kap = (j >> 7) & 15;
        int g = lane >> 2, t = lane & 3;
        int n = ntl * 8 + g;
        int k = kap * 16 + 2 * t + 8 * (j & 1);
        f0 = wl[n * HID + k]; f1 = wl[n * HID + k + 1];
    }
    g_wswz[idx] = packh(f0, f1);
}

// ------- Fused NCA step: M=128 cells/CTA, 512 threads / 16 warps, f16-acc mma -------
__global__ __launch_bounds__(NT, 1)
void nca_step_kernel(const float* __restrict__ hin, float* __restrict__ hout,
                     const float* __restrict__ conv_w,
                     const float* __restrict__ b_first,
                     const float* __restrict__ b_interim)
{
    extern __shared__ float sm[];
    float*    smHalo = sm + OFF_HALO;
    float*    smCwT  = sm + OFF_CW;
    uint32_t* smP    = (uint32_t*)(sm + OFF_P);
    uint32_t* smWFL  = (uint32_t*)(sm + OFF_WFL);
    uint32_t* smAct  = (uint32_t*)(sm + OFF_ACT);
    uint32_t* smWbuf = (uint32_t*)(sm + OFF_WBUF);
    const uint32_t smWbuf_u = (uint32_t)__cvta_generic_to_shared(smWbuf);
    const uint32_t smWFL_u  = (uint32_t)__cvta_generic_to_shared(smWFL);

    const int tid  = threadIdx.x;
    const int lane = tid & 31;
    const int wid  = tid >> 5;
    const int g = lane >> 2;
    const int t = lane & 3;
    const int mw = wid & 1;         // warp m-half: 4 m16-tiles (M=128)
    const int nq = wid >> 1;        // warp n-octant: 4 n8-tiles (N=256)

    const int x0 = blockIdx.x * 16;
    const int y0 = blockIdx.y * 8;
    const int b  = blockIdx.z;
    const float* hbase = hin + (size_t)b * HH * WW * CC;

    // ---- Prologue: G0 = panel0 -> slot0 + w_first/w_last; G1 = panel1; G2 = panel2 ----
    #pragma unroll
    for (int i = 0; i < 2; i++)
        cpa16(smWbuf_u + tid * 32 + i * 16, g_wswz + tid * 8 + i * 4);
    #pragma unroll
    for (int i = 0; i < 2; i++)
        cpa16(smWFL_u + tid * 32 + i * 16, g_wswz + WU_FIRST + tid * 8 + i * 4);
    cpa_commit();
    #pragma unroll
    for (int i = 0; i < 2; i++)
        cpa16(smWbuf_u + 4096 * 4 + tid * 32 + i * 16, g_wswz + 4096 + tid * 8 + i * 4);
    cpa_commit();
    #pragma unroll
    for (int i = 0; i < 2; i++)
        cpa16(smWbuf_u + 2 * 4096 * 4 + tid * 32 + i * 16, g_wswz + 2 * 4096 + tid * 8 + i * 4);
    cpa_commit();

    // ---- Halo (fp32, channel-major [c][y 10][x 18], zero padded) + conv weights ----
    for (int f = tid; f < 2880; f += NT) {
        int xx = f % 18;
        int yy = (f / 18) % 10;
        int c  = f / 180;
        int gx = x0 - 1 + xx;
        int gy = y0 - 1 + yy;
        float v = 0.f;
        if (gy >= 0 && gy < HH && gx >= 0 && gx < WW)
            v = hbase[((size_t)gy * WW + gx) * CC + c];
        smHalo[f] = v;
    }
    for (int f = tid; f < 2304; f += NT)
        smCwT[f] = conv_w[(f & 15) * 144 + (f >> 4)];
    __syncthreads();

    // ---- Conv 3x3 (fp32): thread = (cell m = tid&127, channel group og = tid>>7) ----
    {
        const int m  = tid & 127;
        const int og = tid >> 7;          // 4 output channels per thread (og 0..3)
        const int ly = m >> 4, lx = m & 15;
        float a4[4] = {0.f, 0.f, 0.f, 0.f};
        #pragma unroll
        for (int ci = 0; ci < 16; ci++) {
            #pragma unroll
            for (int r = 0; r < 3; r++) {
                #pragma unroll
                for (int s = 0; s < 3; s++) {
                    float hv = smHalo[ci * 180 + (ly + s) * 18 + (lx + r)];
                    const float* wp = smCwT + (ci * 9 + r * 3 + s) * 16 + og * 4;
                    float4 w0 = *(const float4*)(wp);
                    a4[0] = fmaf(hv, w0.x, a4[0]); a4[1] = fmaf(hv, w0.y, a4[1]);
                    a4[2] = fmaf(hv, w0.z, a4[2]); a4[3] = fmaf(hv, w0.w, a4[3]);
                }
            }
        }
        // pack P into f16 A-frag layout (single k16 tile); channels c = og*4 + j
        const int mt = m >> 4;
        const int r  = m & 15;
        const int gp = r & 7, rh = r >> 3;
        #pragma unroll
        for (int j = 0; j < 4; j += 2) {
            uint32_t u = packh(a4[j], a4[j + 1]);
            int lanep = gp * 4 + (og & 1) * 2 + (j >> 1);
            int slot  = rh + 2 * (og >> 1);
            smP[(mt * 32 + lanep) * 4 + slot] = u;
        }
    }
    cpa_wait2();        // G0 done: panel0 + w_first/w_last resident
    __syncthreads();    // P visible

    // ---- First layer: 16 -> 256, f32-acc mma. Warp tile: 64(M) x 32(N). ----
    float acc[4][4][4];
    {
        #pragma unroll
        for (int nt = 0; nt < 4; nt++) {
            int n = (nq * 4 + nt) * 8 + 2 * t;
            float bz0 = b_first[n];
            float bz1 = b_first[n + 1];
            #pragma unroll
            for (int mt = 0; mt < 4; mt++) {
                acc[mt][nt][0] = bz0; acc[mt][nt][1] = bz1;
                acc[mt][nt][2] = bz0; acc[mt][nt][3] = bz1;
            }
        }
        uint4 af[4];
        #pragma unroll
        for (int mt = 0; mt < 4; mt++)
            af[mt] = ((const uint4*)smP)[(mw * 4 + mt) * 32 + lane];
        #pragma unroll
        for (int nt = 0; nt < 4; nt++) {
            uint2 bch = ((const uint2*)smWFL)[(nq * 4 + nt) * 32 + lane];
            #pragma unroll
            for (int mt = 0; mt < 4; mt++)
                mmah32(acc[mt][nt], af[mt], bch);
        }
        // epilogue: relu + pack, one STS.128 per (mt, kap-pair)
        #pragma unroll
        for (int mt = 0; mt < 4; mt++)
            #pragma unroll
            for (int ntp = 0; ntp < 2; ntp++) {
                const int kap = nq * 2 + ntp;
                uint4 v;
                v.x = packh(fmaxf(acc[mt][2*ntp  ][0], 0.f), fmaxf(acc[mt][2*ntp  ][1], 0.f));
                v.y = packh(fmaxf(acc[mt][2*ntp  ][2], 0.f), fmaxf(acc[mt][2*ntp  ][3], 0.f));
                v.z = packh(fmaxf(acc[mt][2*ntp+1][0], 0.f), fmaxf(acc[mt][2*ntp+1][1], 0.f));
                v.w = packh(fmaxf(acc[mt][2*ntp+1][2], 0.f), fmaxf(acc[mt][2*ntp+1][3], 0.f));
                ((uint4*)smAct)[((mw * 4 + mt) * 16 + kap) * 32 + lane] = v;
            }
    }

    // ---- 3 interim layers: 24 k-panels, 4-slot ring, f16-acc mma + k16 promotion ----
    #pragma unroll 1
    for (int q = 0; q < 24; q++) {
        const int l = q >> 3, p = q & 7;
        cpa_wait2();        // panel q's group complete (2 newer pending)
        __syncthreads();    // panel-q data + (at p==0) prev epilogue visible;
                            // slot (q+3)&3 == (q-1)&3 fully consumed by all warps
        if (q < 21) {
            const uint32_t* src = g_wswz + (size_t)(q + 3) * 4096;
            uint32_t dst = smWbuf_u + ((q + 3) & 3) * (4096 * 4);
            #pragma unroll
            for (int i = 0; i < 2; i++)
                cpa16(dst + tid * 32 + i * 16, src + tid * 8 + i * 4);
        }
        cpa_commit();       // one group per panel (empty for q>=21)

        if (p == 0) {
            #pragma unroll
            for (int nt = 0; nt < 4; nt++) {
                int n = (nq * 4 + nt) * 8 + 2 * t;
                float bz0 = b_interim[l * HID + n];
                float bz1 = b_interim[l * HID + n + 1];
                #pragma unroll
                for (int mt = 0; mt < 4; mt++) {
                    acc[mt][nt][0] = bz0; acc[mt][nt][1] = bz1;
                    acc[mt][nt][2] = bz0; acc[mt][nt][3] = bz1;
                }
            }
        }

        const uint32_t* wb = smWbuf + (q & 3) * 4096;
        #pragma unroll
        for (int kt = 0; kt < 2; kt++) {
            uint4 af[4];
            #pragma unroll
            for (int mt = 0; mt < 4; mt++)
                af[mt] = ((const uint4*)smAct)[((mw * 4 + mt) * 16 + (p * 2 + kt)) * 32 + lane];
            uint2 bch[4];
            #pragma unroll
            for (int nt = 0; nt < 4; nt++)
                bch[nt] = ((const uint2*)wb)[(((nq * 4 + nt) * 2 + kt) * 32 + lane)];
            #pragma unroll
            for (int nt = 0; nt < 4; nt++) {
                uint32_t hc[4][2];
                #pragma unroll
                for (int mt = 0; mt < 4; mt++) { hc[mt][0] = 0u; hc[mt][1] = 0u; }
                #pragma unroll
                for (int mt = 0; mt < 4; mt++)
                    mmah16(hc[mt][0], hc[mt][1], af[mt], bch[nt]);
                // promote k16 partial sums to fp32 accumulators
                #pragma unroll
                for (int mt = 0; mt < 4; mt++) {
                    float2 f0 = __half22float2(*reinterpret_cast<half2*>(&hc[mt][0]));
                    float2 f1 = __half22float2(*reinterpret_cast<half2*>(&hc[mt][1]));
                    acc[mt][nt][0] += f0.x; acc[mt][nt][1] += f0.y;
                    acc[mt][nt][2] += f1.x; acc[mt][nt][3] += f1.y;
                }
            }
        }

        if (p == 7) {
            __syncthreads();   // all warps done READING smAct for this layer
            #pragma unroll
            for (int mt = 0; mt < 4; mt++)
                #pragma unroll
                for (int ntp = 0; ntp < 2; ntp++) {
                    const int kap = nq * 2 + ntp;
                    uint4 v;
                    v.x = packh(fmaxf(acc[mt][2*ntp  ][0], 0.f), fmaxf(acc[mt][2*ntp  ][1], 0.f));
                    v.y = packh(fmaxf(acc[mt][2*ntp  ][2], 0.f), fmaxf(acc[mt][2*ntp  ][3], 0.f));
                    v.z = packh(fmaxf(acc[mt][2*ntp+1][0], 0.f), fmaxf(acc[mt][2*ntp+1][1], 0.f));
                    v.w = packh(fmaxf(acc[mt][2*ntp+1][2], 0.f), fmaxf(acc[mt][2*ntp+1][3], 0.f));
                    ((uint4*)smAct)[((mw * 4 + mt) * 16 + kap) * 32 + lane] = v;
                }
        }
    }

    __syncthreads();   // final acts visible

    // ---- Last layer: 256 -> 16, f32-acc mma + residual + store ----
    // 16 warps: mt = wid&7 (m16 tile), nh = wid>>3 (channel half of 8).
    {
        const int mt = wid & 7;
        const int nh = wid >> 3;
        const uint32_t* wl = smWFL + 2048;
        float acc2[4] = {0.f, 0.f, 0.f, 0.f};
        #pragma unroll 4
        for (int kap = 0; kap < 16; kap++) {
            uint4 a  = ((const uint4*)smAct)[(mt * 16 + kap) * 32 + lane];
            uint2 b0 = ((const uint2*)wl)[(kap * 2 + nh) * 32 + lane];
            mmah32(acc2, a, b0);
        }
        #pragma unroll
        for (int rh = 0; rh < 2; rh++)
            #pragma unroll
            for (int j = 0; j < 2; j++) {
                int ch = nh * 8 + 2 * t + j;
                int m  = mt * 16 + rh * 8 + g;
                int ly = m >> 4, lx = m & 15;
                hout[(((size_t)b * HH + (y0 + ly)) * WW + (x0 + lx)) * CC + ch] =
                    smHalo[ch * 180 + (ly + 1) * 18 + (lx + 1)] + acc2[rh * 2 + j];
            }
    }
}

__global__ void copy_f4_kernel(const float4* __restrict__ src, float4* __restrict__ dst)
{
    int i = blockIdx.x * blockDim.x + threadIdx.x;
    dst[i] = src[i];
}

extern "C" void kernel_launch(void* const* d_in, const int* in_sizes, int n_in,
                              void* d_out, int out_size)
{
    const float* x         = (const float*)d_in[0];
    const float* conv_w    = (const float*)d_in[1];
    const float* w_first   = (const float*)d_in[2];
    const float* b_first   = (const float*)d_in[3];
    const float* w_interim = (const float*)d_in[4];
    const float* b_interim = (const float*)d_in[5];
    const float* w_last    = (const float*)d_in[6];
    // d_in[7] (steps) unused: fixed at 16.

    float* out  = (float*)d_out;            // x_final
    float* hist = out + NELEM;              // history

    cudaFuncSetAttribute(nca_step_kernel,
                         cudaFuncAttributeMaxDynamicSharedMemorySize, SMEM_BYTES);

    preswizzle_kernel<<<(102400 + 255) / 256, 256>>>(w_interim, w_first, w_last);

    // history[0] = x
    copy_f4_kernel<<<NELEM / 4 / 256, 256>>>((const float4*)x, (float4*)hist);

    dim3 grid(WW / 16, HH / 8, BB);
    for (int tstep = 1; tstep <= STEPS; tstep++) {
        nca_step_kernel<<<grid, NT, SMEM_BYTES>>>(
            hist + (size_t)(tstep - 1) * NELEM,
            hist + (size_t)tstep * NELEM,
            conv_w, b_first, b_interim);
    }

    // x_final = history[STEPS]
    copy_f4_kernel<<<NELEM / 4 / 256, 256>>>(
        (const float4*)(hist + (size_t)STEPS * NELEM), (float4*)out);
}

// round 16
// speedup vs baseline: 1.2504x; 1.2504x over previous
#include <cuda_runtime.h>
#include <cstdint>

// Problem constants
#define BB 8
#define HH 128
#define WW 128
#define CC 16
#define HID 256
#define STEPS 16
#define NELEM (BB*HH*WW*CC)   // 2,097,152
#define NT 512

// SMEM layout (32-bit words). CTA tile: 8 y-rows x 16 x-cols = 128 cells (M=128).
#define OFF_HALO 0            // fp32 halo, channel-major: 16ch * 10y * 18x = 2880
#define OFF_CW   2880         // fp32 transposed conv w: [ci*9+rs][16 o] = 2304
#define OFF_P    5184         // P frags (bf16 packed): 8mt * 32lane * 4 u32 = 1024
#define OFF_WFL  6208         // w_first (2048 u32) + w_last (2048 u32) = 4096
#define OFF_ACT  10304        // acts: 8mt * 16ktile * 32lane * 4 u32 = 16384
#define OFF_WBUF 26688        // 3-slot K64-panel ring: 3 * 8192 u32 = 24576
#define SMEM_WORDS 51264
#define SMEM_BYTES (SMEM_WORDS*4)   // 205,056 B

// Pre-swizzled bf16-packed weights (u32 = 2 bf16), written once per launch.
// Same gmem layout as the validated R10 kernel: 24 k32-panels of 4096 u32 each;
// a K64 panel j is the two contiguous k32-panels [j*8192, (j+1)*8192).
// k32-panel word idx = ((nt*2+kt)*32+lane)*2+b ;
//   n = nt*8+(lane>>2), k = p32*32 + kt*16 + 2*(lane&3) + 8*b  (pair k,k+1)
#define WU_FIRST 98304
#define WU_LAST  100352
__device__ uint32_t g_wswz[102400];

__device__ __forceinline__ uint32_t packbf(float lo, float hi) {
    uint32_t u;
    asm("cvt.rn.bf16x2.f32 %0, %1, %2;" : "=r"(u) : "f"(hi), "f"(lo));
    return u;
}

__device__ __forceinline__ void mmabf(float* c, const uint4& a, const uint2& b) {
    asm volatile(
        "mma.sync.aligned.m16n8k16.row.col.f32.bf16.bf16.f32 "
        "{%0,%1,%2,%3}, {%4,%5,%6,%7}, {%8,%9}, {%0,%1,%2,%3};\n"
        : "+f"(c[0]), "+f"(c[1]), "+f"(c[2]), "+f"(c[3])
        : "r"(a.x), "r"(a.y), "r"(a.z), "r"(a.w), "r"(b.x), "r"(b.y));
}

__device__ __forceinline__ void cpa16(uint32_t dst, const void* src) {
    asm volatile("cp.async.cg.shared.global [%0], [%1], 16;\n" :: "r"(dst), "l"(src));
}
__device__ __forceinline__ void cpa_commit() { asm volatile("cp.async.commit_group;\n" ::: "memory"); }
__device__ __forceinline__ void cpa_wait1()  { asm volatile("cp.async.wait_group 1;\n"  ::: "memory"); }

// ---------------- Pre-swizzle weights into packed-bf16 mma fragment order -------------
// (identical to the validated R10 kernel)
__global__ void preswizzle_kernel(const float* __restrict__ wi,
                                  const float* __restrict__ wf,
                                  const float* __restrict__ wl)
{
    int idx = blockIdx.x * blockDim.x + threadIdx.x;
    if (idx >= 102400) return;
    float f0, f1;
    if (idx < WU_FIRST) {
        // ((((l*8+p)*32+nt)*2+kt)*32+lane)*2 + b
        int lane = (idx >> 1) & 31, kt = (idx >> 6) & 1, nt = (idx >> 7) & 31;
        int p = (idx >> 12) & 7, l = idx >> 15;
        int g = lane >> 2, t = lane & 3;
        int n = nt * 8 + g;
        int k = p * 32 + kt * 16 + 2 * t + 8 * (idx & 1);
        const float* row = wi + (l * HID + n) * HID;
        f0 = row[k]; f1 = row[k + 1];
    } else if (idx < WU_LAST) {
        int j = idx - WU_FIRST;          // (nt*32+lane)*2 + b
        int lane = (j >> 1) & 31, nt = (j >> 6) & 31;
        int g = lane >> 2, t = lane & 3;
        int n = nt * 8 + g;
        int k = 2 * t + 8 * (j & 1);
        f0 = wf[n * CC + k]; f1 = wf[n * CC + k + 1];
    } else {
        int j = idx - WU_LAST;           // ((kap*2+ntl)*32+lane)*2 + b
        int lane = (j >> 1) & 31, ntl = (j >> 6) & 1, kap = (j >> 7) & 15;
        int g = lane >> 2, t = lane & 3;
        int n = ntl * 8 + g;
        int k = kap * 16 + 2 * t + 8 * (j & 1);
        f0 = wl[n * HID + k]; f1 = wl[n * HID + k + 1];
    }
    g_wswz[idx] = packbf(f0, f1);
}

// ------- Fused NCA step: M=128 cells/CTA, 512 threads / 16 warps, K64 panels -------
__global__ __launch_bounds__(NT, 1)
void nca_step_kernel(const float* __restrict__ hin, float* __restrict__ hout,
                     const float* __restrict__ conv_w,
                     const float* __restrict__ b_first,
                     const float* __restrict__ b_interim)
{
    extern __shared__ float sm[];
    float*    smHalo = sm + OFF_HALO;
    float*    smCwT  = sm + OFF_CW;
    uint32_t* smP    = (uint32_t*)(sm + OFF_P);
    uint32_t* smWFL  = (uint32_t*)(sm + OFF_WFL);
    uint32_t* smAct  = (uint32_t*)(sm + OFF_ACT);
    uint32_t* smWbuf = (uint32_t*)(sm + OFF_WBUF);
    const uint32_t smWbuf_u = (uint32_t)__cvta_generic_to_shared(smWbuf);
    const uint32_t smWFL_u  = (uint32_t)__cvta_generic_to_shared(smWFL);

    const int tid  = threadIdx.x;
    const int lane = tid & 31;
    const int wid  = tid >> 5;
    const int g = lane >> 2;
    const int t = lane & 3;
    const int mw = wid & 1;         // warp m-half: 4 m16-tiles (M=128)
    const int nq = wid >> 1;        // warp n-octant: 4 n8-tiles (N=256)

    const int x0 = blockIdx.x * 16;
    const int y0 = blockIdx.y * 8;
    const int b  = blockIdx.z;
    const float* hbase = hin + (size_t)b * HH * WW * CC;

    // ---- Prologue: G0 = K64 panel0 -> slot0 + w_first/w_last; G1 = panel1 -> slot1 ----
    #pragma unroll
    for (int i = 0; i < 4; i++)
        cpa16(smWbuf_u + tid * 64 + i * 16, g_wswz + tid * 16 + i * 4);
    #pragma unroll
    for (int i = 0; i < 2; i++)
        cpa16(smWFL_u + tid * 32 + i * 16, g_wswz + WU_FIRST + tid * 8 + i * 4);
    cpa_commit();
    #pragma unroll
    for (int i = 0; i < 4; i++)
        cpa16(smWbuf_u + 8192 * 4 + tid * 64 + i * 16, g_wswz + 8192 + tid * 16 + i * 4);
    cpa_commit();

    // ---- Halo (fp32, channel-major [c][y 10][x 18], zero padded) + conv weights ----
    for (int f = tid; f < 2880; f += NT) {
        int xx = f % 18;
        int yy = (f / 18) % 10;
        int c  = f / 180;
        int gx = x0 - 1 + xx;
        int gy = y0 - 1 + yy;
        float v = 0.f;
        if (gy >= 0 && gy < HH && gx >= 0 && gx < WW)
            v = hbase[((size_t)gy * WW + gx) * CC + c];
        smHalo[f] = v;
    }
    for (int f = tid; f < 2304; f += NT)
        smCwT[f] = conv_w[(f & 15) * 144 + (f >> 4)];
    __syncthreads();

    // ---- Conv 3x3 (fp32): thread = (cell m = tid&127, channel group og = tid>>7) ----
    {
        const int m  = tid & 127;
        const int og = tid >> 7;          // 4 output channels per thread (og 0..3)
        const int ly = m >> 4, lx = m & 15;
        float a4[4] = {0.f, 0.f, 0.f, 0.f};
        #pragma unroll
        for (int ci = 0; ci < 16; ci++) {
            #pragma unroll
            for (int r = 0; r < 3; r++) {
                #pragma unroll
                for (int s = 0; s < 3; s++) {
                    float hv = smHalo[ci * 180 + (ly + s) * 18 + (lx + r)];
                    const float* wp = smCwT + (ci * 9 + r * 3 + s) * 16 + og * 4;
                    float4 w0 = *(const float4*)(wp);
                    a4[0] = fmaf(hv, w0.x, a4[0]); a4[1] = fmaf(hv, w0.y, a4[1]);
                    a4[2] = fmaf(hv, w0.z, a4[2]); a4[3] = fmaf(hv, w0.w, a4[3]);
                }
            }
        }
        // pack P into bf16 A-frag layout (single k16 tile); channels c = og*4 + j
        const int mt = m >> 4;
        const int r  = m & 15;
        const int gp = r & 7, rh = r >> 3;
        #pragma unroll
        for (int j = 0; j < 4; j += 2) {
            uint32_t u = packbf(a4[j], a4[j + 1]);
            int lanep = gp * 4 + (og & 1) * 2 + (j >> 1);
            int slot  = rh + 2 * (og >> 1);
            smP[(mt * 32 + lanep) * 4 + slot] = u;
        }
    }
    cpa_wait1();        // G0 done: panel0 + w_first/w_last resident (G1 may pend)
    __syncthreads();    // P visible

    // ---- First layer: 16 -> 256 via bf16 mma. Warp tile: 64(M) x 32(N). ----
    float acc[4][4][4];
    {
        #pragma unroll
        for (int nt = 0; nt < 4; nt++) {
            int n = (nq * 4 + nt) * 8 + 2 * t;
            float bz0 = b_first[n];
            float bz1 = b_first[n + 1];
            #pragma unroll
            for (int mt = 0; mt < 4; mt++) {
                acc[mt][nt][0] = bz0; acc[mt][nt][1] = bz1;
                acc[mt][nt][2] = bz0; acc[mt][nt][3] = bz1;
            }
        }
        uint4 af[4];
        #pragma unroll
        for (int mt = 0; mt < 4; mt++)
            af[mt] = ((const uint4*)smP)[(mw * 4 + mt) * 32 + lane];
        #pragma unroll
        for (int nt = 0; nt < 4; nt++) {
            uint2 bch = ((const uint2*)smWFL)[(nq * 4 + nt) * 32 + lane];
            #pragma unroll
            for (int mt = 0; mt < 4; mt++)
                mmabf(acc[mt][nt], af[mt], bch);
        }
        // epilogue: relu + pack, one STS.128 per (mt, kap-pair)
        #pragma unroll
        for (int mt = 0; mt < 4; mt++)
            #pragma unroll
            for (int ntp = 0; ntp < 2; ntp++) {
                const int kap = nq * 2 + ntp;
                uint4 v;
                v.x = packbf(fmaxf(acc[mt][2*ntp  ][0], 0.f), fmaxf(acc[mt][2*ntp  ][1], 0.f));
                v.y = packbf(fmaxf(acc[mt][2*ntp  ][2], 0.f), fmaxf(acc[mt][2*ntp  ][3], 0.f));
                v.z = packbf(fmaxf(acc[mt][2*ntp+1][0], 0.f), fmaxf(acc[mt][2*ntp+1][1], 0.f));
                v.w = packbf(fmaxf(acc[mt][2*ntp+1][2], 0.f), fmaxf(acc[mt][2*ntp+1][3], 0.f));
                ((uint4*)smAct)[((mw * 4 + mt) * 16 + kap) * 32 + lane] = v;
            }
    }

    // ---- 3 interim layers: 12 K64-panels, 3-slot ring, prefetch distance 2 ----
    #pragma unroll 1
    for (int q = 0; q < 12; q++) {
        const int l = q >> 2, p = q & 3;
        cpa_wait1();        // fetch(q) complete (fetch(q+1) may pend)
        __syncthreads();    // panel-q data + (at p==0) prev epilogue visible;
                            // slot (q+2)%3 == slot of panel q-1, fully consumed
        if (q < 10) {
            const uint32_t* src = g_wswz + (size_t)(q + 2) * 8192;
            uint32_t dst = smWbuf_u + ((q + 2) % 3) * (8192 * 4);
            #pragma unroll
            for (int i = 0; i < 4; i++)
                cpa16(dst + tid * 64 + i * 16, src + tid * 16 + i * 4);
        }
        cpa_commit();       // one group per panel (empty for q>=10)

        if (p == 0) {
            #pragma unroll
            for (int nt = 0; nt < 4; nt++) {
                int n = (nq * 4 + nt) * 8 + 2 * t;
                float bz0 = b_interim[l * HID + n];
                float bz1 = b_interim[l * HID + n + 1];
                #pragma unroll
                for (int mt = 0; mt < 4; mt++) {
                    acc[mt][nt][0] = bz0; acc[mt][nt][1] = bz1;
                    acc[mt][nt][2] = bz0; acc[mt][nt][3] = bz1;
                }
            }
        }

        const uint32_t* wb = smWbuf + (q % 3) * 8192;
        #pragma unroll
        for (int kt = 0; kt < 4; kt++) {        // four k16 steps within the K64 panel
            const uint32_t* wsub = wb + (kt >> 1) * 4096;
            uint2 bch[4];
            #pragma unroll
            for (int nt = 0; nt < 4; nt++)
                bch[nt] = ((const uint2*)wsub)[(((nq * 4 + nt) * 2 + (kt & 1)) * 32 + lane)];
            uint4 af[4];
            #pragma unroll
            for (int mt = 0; mt < 4; mt++)
                af[mt] = ((const uint4*)smAct)[((mw * 4 + mt) * 16 + (p * 4 + kt)) * 32 + lane];
            #pragma unroll
            for (int mt = 0; mt < 4; mt++)
                #pragma unroll
                for (int nt = 0; nt < 4; nt++)
                    mmabf(acc[mt][nt], af[mt], bch[nt]);
        }

        if (p == 3) {
            __syncthreads();   // all warps done READING smAct for this layer
            #pragma unroll
            for (int mt = 0; mt < 4; mt++)
                #pragma unroll
                for (int ntp = 0; ntp < 2; ntp++) {
                    const int kap = nq * 2 + ntp;
                    uint4 v;
                    v.x = packbf(fmaxf(acc[mt][2*ntp  ][0], 0.f), fmaxf(acc[mt][2*ntp  ][1], 0.f));
                    v.y = packbf(fmaxf(acc[mt][2*ntp  ][2], 0.f), fmaxf(acc[mt][2*ntp  ][3], 0.f));
                    v.z = packbf(fmaxf(acc[mt][2*ntp+1][0], 0.f), fmaxf(acc[mt][2*ntp+1][1], 0.f));
                    v.w = packbf(fmaxf(acc[mt][2*ntp+1][2], 0.f), fmaxf(acc[mt][2*ntp+1][3], 0.f));
                    ((uint4*)smAct)[((mw * 4 + mt) * 16 + kap) * 32 + lane] = v;
                }
        }
    }

    __syncthreads();   // final acts visible

    // ---- Last layer: 256 -> 16 via bf16 mma + residual + store ----
    // 16 warps: mt = wid&7 (m16 tile), nh = wid>>3 (channel half of 8).
    {
        const int mt = wid & 7;
        const int nh = wid >> 3;
        const uint32_t* wl = smWFL + 2048;
        float acc2[4] = {0.f, 0.f, 0.f, 0.f};
        #pragma unroll 4
        for (int kap = 0; kap < 16; kap++) {
            uint4 a  = ((const uint4*)smAct)[(mt * 16 + kap) * 32 + lane];
            uint2 b0 = ((const uint2*)wl)[(kap * 2 + nh) * 32 + lane];
            mmabf(acc2, a, b0);
        }
        #pragma unroll
        for (int rh = 0; rh < 2; rh++)
            #pragma unroll
            for (int j = 0; j < 2; j++) {
                int ch = nh * 8 + 2 * t + j;
                int m  = mt * 16 + rh * 8 + g;
                int ly = m >> 4, lx = m & 15;
                hout[(((size_t)b * HH + (y0 + ly)) * WW + (x0 + lx)) * CC + ch] =
                    smHalo[ch * 180 + (ly + 1) * 18 + (lx + 1)] + acc2[rh * 2 + j];
            }
    }
}

__global__ void copy_f4_kernel(const float4* __restrict__ src, float4* __restrict__ dst)
{
    int i = blockIdx.x * blockDim.x + threadIdx.x;
    dst[i] = src[i];
}

extern "C" void kernel_launch(void* const* d_in, const int* in_sizes, int n_in,
                              void* d_out, int out_size)
{
    const float* x         = (const float*)d_in[0];
    const float* conv_w    = (const float*)d_in[1];
    const float* w_first   = (const float*)d_in[2];
    const float* b_first   = (const float*)d_in[3];
    const float* w_interim = (const float*)d_in[4];
    const float* b_interim = (const float*)d_in[5];
    const float* w_last    = (const float*)d_in[6];
    // d_in[7] (steps) unused: fixed at 16.

    float* out  = (float*)d_out;            // x_final
    float* hist = out + NELEM;              // history

    cudaFuncSetAttribute(nca_step_kernel,
                         cudaFuncAttributeMaxDynamicSharedMemorySize, SMEM_BYTES);

    preswizzle_kernel<<<(102400 + 255) / 256, 256>>>(w_interim, w_first, w_last);

    // history[0] = x
    copy_f4_kernel<<<NELEM / 4 / 256, 256>>>((const float4*)x, (float4*)hist);

    dim3 grid(WW / 16, HH / 8, BB);
    for (int tstep = 1; tstep <= STEPS; tstep++) {
        nca_step_kernel<<<grid, NT, SMEM_BYTES>>>(
            hist + (size_t)(tstep - 1) * NELEM,
            hist + (size_t)tstep * NELEM,
            conv_w, b_first, b_interim);
    }

    // x_final = history[STEPS]
    copy_f4_kernel<<<NELEM / 4 / 256, 256>>>(
        (const float4*)(hist + (size_t)STEPS * NELEM), (float4*)out);
}

// round 17
// speedup vs baseline: 1.3692x; 1.0950x over previous
#include <cuda_runtime.h>
#include <cstdint>

// Problem constants
#define BB 8
#define HH 128
#define WW 128
#define CC 16
#define HID 256
#define STEPS 16
#define NELEM (BB*HH*WW*CC)   // 2,097,152
#define NT 512

// SMEM layout (32-bit words). CTA tile: 8 y-rows x 16 x-cols = 128 cells (M=128).
#define OFF_HALO 0            // fp32 halo, channel-major: 16ch * 180 cells = 2880 f
#define OFF_HB   2880         // bf16-packed halo: 180 cells * pitch 9 u32 = 1620 u32
#define OFF_CWF  4500         // conv-w B-frags: 9 slices * 2 nh * 32 lanes * 2 u32 = 1152
#define OFF_P    5652         // P frags (bf16 packed): 8mt * 32lane * 4 u32 = 1024
#define OFF_WFL  6676         // w_first (2048 u32) + w_last (2048 u32) = 4096
#define OFF_ACT  10772        // acts: 8mt * 16ktile * 32lane * 4 u32 = 16384
#define OFF_WBUF 27156        // 4-slot panel ring: 4 * 4096 u32 = 16384
#define SMEM_WORDS 43540
#define SMEM_BYTES (SMEM_WORDS*4)   // 174,160 B

// Pre-swizzled bf16-packed weights (u32 = 2 bf16), written once per launch.
// interim: 24 panels (l*8+p) * 4096; u32 idx in panel = ((nt*2+kt)*32+lane)*2+b
//          n = nt*8+(lane>>2), k = p*32 + kt*16 + 2*(lane&3) + 8*b  (pair k,k+1)
// conv:    idx = GW_CONV + ((slice*2+nh)*32+lane)*2 + b ; slice = r*3+s,
//          n = nh*8+(lane>>2), ci = 2*(lane&3) + 8*b (pair ci,ci+1)
#define WU_FIRST 98304
#define WU_LAST  100352
#define GW_CONV  102400
#define GW_TOTAL 103552
__device__ uint32_t g_wswz[GW_TOTAL];

__device__ __forceinline__ uint32_t packbf(float lo, float hi) {
    uint32_t u;
    asm("cvt.rn.bf16x2.f32 %0, %1, %2;" : "=r"(u) : "f"(hi), "f"(lo));
    return u;
}

__device__ __forceinline__ void mmabf(float* c, const uint4& a, const uint2& b) {
    asm volatile(
        "mma.sync.aligned.m16n8k16.row.col.f32.bf16.bf16.f32 "
        "{%0,%1,%2,%3}, {%4,%5,%6,%7}, {%8,%9}, {%0,%1,%2,%3};\n"
        : "+f"(c[0]), "+f"(c[1]), "+f"(c[2]), "+f"(c[3])
        : "r"(a.x), "r"(a.y), "r"(a.z), "r"(a.w), "r"(b.x), "r"(b.y));
}

__device__ __forceinline__ void cpa16(uint32_t dst, const void* src) {
    asm volatile("cp.async.cg.shared.global [%0], [%1], 16;\n" :: "r"(dst), "l"(src));
}
__device__ __forceinline__ void cpa_commit() { asm volatile("cp.async.commit_group;\n" ::: "memory"); }
__device__ __forceinline__ void cpa_wait2()  { asm volatile("cp.async.wait_group 2;\n"  ::: "memory"); }

// ---------------- Pre-swizzle weights into packed-bf16 mma fragment order -------------
__global__ void preswizzle_kernel(const float* __restrict__ wi,
                                  const float* __restrict__ wf,
                                  const float* __restrict__ wl,
                                  const float* __restrict__ cw)
{
    int idx = blockIdx.x * blockDim.x + threadIdx.x;
    if (idx >= GW_TOTAL) return;
    float f0, f1;
    if (idx < WU_FIRST) {
        // ((((l*8+p)*32+nt)*2+kt)*32+lane)*2 + b
        int lane = (idx >> 1) & 31, kt = (idx >> 6) & 1, nt = (idx >> 7) & 31;
        int p = (idx >> 12) & 7, l = idx >> 15;
        int g = lane >> 2, t = lane & 3;
        int n = nt * 8 + g;
        int k = p * 32 + kt * 16 + 2 * t + 8 * (idx & 1);
        const float* row = wi + (l * HID + n) * HID;
        f0 = row[k]; f1 = row[k + 1];
    } else if (idx < WU_LAST) {
        int j = idx - WU_FIRST;          // (nt*32+lane)*2 + b
        int lane = (j >> 1) & 31, nt = (j >> 6) & 31;
        int g = lane >> 2, t = lane & 3;
        int n = nt * 8 + g;
        int k = 2 * t + 8 * (j & 1);
        f0 = wf[n * CC + k]; f1 = wf[n * CC + k + 1];
    } else if (idx < GW_CONV) {
        int j = idx - WU_LAST;           // ((kap*2+ntl)*32+lane)*2 + b
        int lane = (j >> 1) & 31, ntl = (j >> 6) & 1, kap = (j >> 7) & 15;
        int g = lane >> 2, t = lane & 3;
        int n = ntl * 8 + g;
        int k = kap * 16 + 2 * t + 8 * (j & 1);
        f0 = wl[n * HID + k]; f1 = wl[n * HID + k + 1];
    } else {
        // conv B-frags: cw layout [o][ci][r][s] = cw[o*144 + ci*9 + r*3+s]
        int j = idx - GW_CONV;           // ((slice*2+nh)*32+lane)*2 + b
        int lane = (j >> 1) & 31, nh = (j >> 6) & 1, slice = j >> 7;  // 0..8
        int g = lane >> 2, t = lane & 3;
        int n = nh * 8 + g;
        int ci = 2 * t + 8 * (j & 1);
        f0 = cw[n * 144 + ci * 9 + slice];
        f1 = cw[n * 144 + (ci + 1) * 9 + slice];
    }
    g_wswz[idx] = packbf(f0, f1);
}

// ------- Fused NCA step: M=128 cells/CTA, 512 threads / 16 warps, conv via HMMA -------
__global__ __launch_bounds__(NT, 1)
void nca_step_kernel(const float* __restrict__ hin, float* __restrict__ hout,
                     const float* __restrict__ b_first,
                     const float* __restrict__ b_interim)
{
    extern __shared__ float sm[];
    float*    smHalo = sm + OFF_HALO;
    uint32_t* smHB   = (uint32_t*)(sm + OFF_HB);
    uint32_t* smCwF  = (uint32_t*)(sm + OFF_CWF);
    uint32_t* smP    = (uint32_t*)(sm + OFF_P);
    uint32_t* smWFL  = (uint32_t*)(sm + OFF_WFL);
    uint32_t* smAct  = (uint32_t*)(sm + OFF_ACT);
    uint32_t* smWbuf = (uint32_t*)(sm + OFF_WBUF);
    const uint32_t smWbuf_u = (uint32_t)__cvta_generic_to_shared(smWbuf);
    const uint32_t smWFL_u  = (uint32_t)__cvta_generic_to_shared(smWFL);
    const uint32_t smCwF_u  = (uint32_t)__cvta_generic_to_shared(smCwF);

    const int tid  = threadIdx.x;
    const int lane = tid & 31;
    const int wid  = tid >> 5;
    const int g = lane >> 2;
    const int t = lane & 3;
    const int mw = wid & 1;         // warp m-half: 4 m16-tiles (M=128)
    const int nq = wid >> 1;        // warp n-octant: 4 n8-tiles (N=256)

    const int x0 = blockIdx.x * 16;
    const int y0 = blockIdx.y * 8;
    const int b  = blockIdx.z;
    const float* hbase = hin + (size_t)b * HH * WW * CC;

    // ---- Prologue: G0 = panel0 + w_first/w_last + conv frags; G1 = panel1; G2 = panel2
    #pragma unroll
    for (int i = 0; i < 2; i++)
        cpa16(smWbuf_u + tid * 32 + i * 16, g_wswz + tid * 8 + i * 4);
    #pragma unroll
    for (int i = 0; i < 2; i++)
        cpa16(smWFL_u + tid * 32 + i * 16, g_wswz + WU_FIRST + tid * 8 + i * 4);
    if (tid < 288)
        cpa16(smCwF_u + tid * 16, g_wswz + GW_CONV + tid * 4);
    cpa_commit();
    #pragma unroll
    for (int i = 0; i < 2; i++)
        cpa16(smWbuf_u + 4096 * 4 + tid * 32 + i * 16, g_wswz + 4096 + tid * 8 + i * 4);
    cpa_commit();
    #pragma unroll
    for (int i = 0; i < 2; i++)
        cpa16(smWbuf_u + 2 * 4096 * 4 + tid * 32 + i * 16, g_wswz + 2 * 4096 + tid * 8 + i * 4);
    cpa_commit();

    // ---- Halo: coalesced float4 loads; dual-write fp32 (residual) + bf16 pairs (conv A)
    // 180 halo cells (10y x 18x, zero padded), 4 float4 per cell.
    for (int f = tid; f < 720; f += NT) {
        int cell = f >> 2, j = f & 3;
        int yy = cell / 18, xx = cell - yy * 18;
        int gy = y0 - 1 + yy, gx = x0 - 1 + xx;
        float4 v = make_float4(0.f, 0.f, 0.f, 0.f);
        if (gy >= 0 && gy < HH && gx >= 0 && gx < WW)
            v = *(const float4*)(hbase + ((size_t)gy * WW + gx) * CC + j * 4);
        smHalo[(4 * j + 0) * 180 + cell] = v.x;
        smHalo[(4 * j + 1) * 180 + cell] = v.y;
        smHalo[(4 * j + 2) * 180 + cell] = v.z;
        smHalo[(4 * j + 3) * 180 + cell] = v.w;
        smHB[cell * 9 + 2 * j]     = packbf(v.x, v.y);
        smHB[cell * 9 + 2 * j + 1] = packbf(v.z, v.w);
    }
    __syncthreads();    // halo + hb visible
    cpa_wait2();        // G0 done: panel0 + w_first/w_last + conv frags resident

    // ---- Conv 3x3 via HMMA: warp = (mt = wid&7, nh = wid>>3); 9 k16 slices ----
    {
        const int mt = wid & 7;      // output y-row (tile of 16 x-cells)
        const int nh = wid >> 3;     // output channel half (8 channels)
        float c4[4] = {0.f, 0.f, 0.f, 0.f};
        #pragma unroll
        for (int s = 0; s < 3; s++) {
            #pragma unroll
            for (int r = 0; r < 3; r++) {
                const int slice = r * 3 + s;
                const int base = ((mt + s) * 18 + (g + r)) * 9;
                uint4 a;
                a.x = smHB[base + t];            // row lx=g,   ci pair t
                a.y = smHB[base + 72 + t];       // row lx=g+8 (+8 cells * 9)
                a.z = smHB[base + t + 4];        // row g,   ci pair t+4
                a.w = smHB[base + 72 + t + 4];   // row g+8, ci pair t+4
                uint2 bf = ((const uint2*)smCwF)[(slice * 2 + nh) * 32 + lane];
                mmabf(c4, a, bf);
            }
        }
        // pack P into first-layer A-frag layout: lanep == lane, slots (2nh, 2nh+1)
        uint32_t u0 = packbf(c4[0], c4[1]);      // row g,   ch (nh*8+2t, +1)
        uint32_t u1 = packbf(c4[2], c4[3]);      // row g+8
        *(uint2*)&smP[(mt * 32 + lane) * 4 + 2 * nh] = make_uint2(u0, u1);
    }
    __syncthreads();    // P visible

    // ---- First layer: 16 -> 256 via bf16 mma. Warp tile: 64(M) x 32(N). ----
    float acc[4][4][4];
    {
        #pragma unroll
        for (int nt = 0; nt < 4; nt++) {
            int n = (nq * 4 + nt) * 8 + 2 * t;
            float bz0 = b_first[n];
            float bz1 = b_first[n + 1];
            #pragma unroll
            for (int mt = 0; mt < 4; mt++) {
                acc[mt][nt][0] = bz0; acc[mt][nt][1] = bz1;
                acc[mt][nt][2] = bz0; acc[mt][nt][3] = bz1;
            }
        }
        uint4 af[4];
        #pragma unroll
        for (int mt = 0; mt < 4; mt++)
            af[mt] = ((const uint4*)smP)[(mw * 4 + mt) * 32 + lane];
        #pragma unroll
        for (int nt = 0; nt < 4; nt++) {
            uint2 bch = ((const uint2*)smWFL)[(nq * 4 + nt) * 32 + lane];
            #pragma unroll
            for (int mt = 0; mt < 4; mt++)
                mmabf(acc[mt][nt], af[mt], bch);
        }
        // epilogue: relu + pack, one STS.128 per (mt, kap-pair)
        #pragma unroll
        for (int mt = 0; mt < 4; mt++)
            #pragma unroll
            for (int ntp = 0; ntp < 2; ntp++) {
                const int kap = nq * 2 + ntp;
                uint4 v;
                v.x = packbf(fmaxf(acc[mt][2*ntp  ][0], 0.f), fmaxf(acc[mt][2*ntp  ][1], 0.f));
                v.y = packbf(fmaxf(acc[mt][2*ntp  ][2], 0.f), fmaxf(acc[mt][2*ntp  ][3], 0.f));
                v.z = packbf(fmaxf(acc[mt][2*ntp+1][0], 0.f), fmaxf(acc[mt][2*ntp+1][1], 0.f));
                v.w = packbf(fmaxf(acc[mt][2*ntp+1][2], 0.f), fmaxf(acc[mt][2*ntp+1][3], 0.f));
                ((uint4*)smAct)[((mw * 4 + mt) * 16 + kap) * 32 + lane] = v;
            }
    }

    // ---- 3 interim layers: 24 k-panels, 4-slot ring prefetched 3 ahead ----
    #pragma unroll 1
    for (int q = 0; q < 24; q++) {
        const int l = q >> 3, p = q & 7;
        cpa_wait2();        // panel q's group complete (2 newer pending)
        __syncthreads();    // panel-q data + (at p==0) prev epilogue visible;
                            // slot (q+3)&3 == (q-1)&3 fully consumed by all warps
        if (q < 21) {
            const uint32_t* src = g_wswz + (size_t)(q + 3) * 4096;
            uint32_t dst = smWbuf_u + ((q + 3) & 3) * (4096 * 4);
            #pragma unroll
            for (int i = 0; i < 2; i++)
                cpa16(dst + tid * 32 + i * 16, src + tid * 8 + i * 4);
        }
        cpa_commit();       // one group per panel (empty for q>=21)

        if (p == 0) {
            #pragma unroll
            for (int nt = 0; nt < 4; nt++) {
                int n = (nq * 4 + nt) * 8 + 2 * t;
                float bz0 = b_interim[l * HID + n];
                float bz1 = b_interim[l * HID + n + 1];
                #pragma unroll
                for (int mt = 0; mt < 4; mt++) {
                    acc[mt][nt][0] = bz0; acc[mt][nt][1] = bz1;
                    acc[mt][nt][2] = bz0; acc[mt][nt][3] = bz1;
                }
            }
        }

        const uint32_t* wb = smWbuf + (q & 3) * 4096;
        #pragma unroll
        for (int kt = 0; kt < 2; kt++) {
            uint2 bch[4];
            #pragma unroll
            for (int nt = 0; nt < 4; nt++)
                bch[nt] = ((const uint2*)wb)[(((nq * 4 + nt) * 2 + kt) * 32 + lane)];
            uint4 af[4];
            #pragma unroll
            for (int mt = 0; mt < 4; mt++)
                af[mt] = ((const uint4*)smAct)[((mw * 4 + mt) * 16 + (p * 2 + kt)) * 32 + lane];
            #pragma unroll
            for (int mt = 0; mt < 4; mt++)
                #pragma unroll
                for (int nt = 0; nt < 4; nt++)
                    mmabf(acc[mt][nt], af[mt], bch[nt]);
        }

        if (p == 7) {
            __syncthreads();   // all warps done READING smAct for this layer
            #pragma unroll
            for (int mt = 0; mt < 4; mt++)
                #pragma unroll
                for (int ntp = 0; ntp < 2; ntp++) {
                    const int kap = nq * 2 + ntp;
                    uint4 v;
                    v.x = packbf(fmaxf(acc[mt][2*ntp  ][0], 0.f), fmaxf(acc[mt][2*ntp  ][1], 0.f));
                    v.y = packbf(fmaxf(acc[mt][2*ntp  ][2], 0.f), fmaxf(acc[mt][2*ntp  ][3], 0.f));
                    v.z = packbf(fmaxf(acc[mt][2*ntp+1][0], 0.f), fmaxf(acc[mt][2*ntp+1][1], 0.f));
                    v.w = packbf(fmaxf(acc[mt][2*ntp+1][2], 0.f), fmaxf(acc[mt][2*ntp+1][3], 0.f));
                    ((uint4*)smAct)[((mw * 4 + mt) * 16 + kap) * 32 + lane] = v;
                }
        }
    }

    __syncthreads();   // final acts visible

    // ---- Last layer: 256 -> 16 via bf16 mma + residual + store ----
    // 16 warps: mt = wid&7 (m16 tile), nh = wid>>3 (channel half of 8).
    {
        const int mt = wid & 7;
        const int nh = wid >> 3;
        const uint32_t* wl = smWFL + 2048;
        float acc2[4] = {0.f, 0.f, 0.f, 0.f};
        #pragma unroll 4
        for (int kap = 0; kap < 16; kap++) {
            uint4 a  = ((const uint4*)smAct)[(mt * 16 + kap) * 32 + lane];
            uint2 b0 = ((const uint2*)wl)[(kap * 2 + nh) * 32 + lane];
            mmabf(acc2, a, b0);
        }
        #pragma unroll
        for (int rh = 0; rh < 2; rh++)
            #pragma unroll
            for (int j = 0; j < 2; j++) {
                int ch = nh * 8 + 2 * t + j;
                int m  = mt * 16 + rh * 8 + g;
                int ly = m >> 4, lx = m & 15;
                hout[(((size_t)b * HH + (y0 + ly)) * WW + (x0 + lx)) * CC + ch] =
                    smHalo[ch * 180 + (ly + 1) * 18 + (lx + 1)] + acc2[rh * 2 + j];
            }
    }
}

__global__ void copy_f4_kernel(const float4* __restrict__ src, float4* __restrict__ dst)
{
    int i = blockIdx.x * blockDim.x + threadIdx.x;
    dst[i] = src[i];
}

extern "C" void kernel_launch(void* const* d_in, const int* in_sizes, int n_in,
                              void* d_out, int out_size)
{
    const float* x         = (const float*)d_in[0];
    const float* conv_w    = (const float*)d_in[1];
    const float* w_first   = (const float*)d_in[2];
    const float* b_first   = (const float*)d_in[3];
    const float* w_interim = (const float*)d_in[4];
    const float* b_interim = (const float*)d_in[5];
    const float* w_last    = (const float*)d_in[6];
    // d_in[7] (steps) unused: fixed at 16.

    float* out  = (float*)d_out;            // x_final
    float* hist = out + NELEM;              // history

    cudaFuncSetAttribute(nca_step_kernel,
                         cudaFuncAttributeMaxDynamicSharedMemorySize, SMEM_BYTES);

    preswizzle_kernel<<<(GW_TOTAL + 255) / 256, 256>>>(w_interim, w_first, w_last, conv_w);

    // history[0] = x
    copy_f4_kernel<<<NELEM / 4 / 256, 256>>>((const float4*)x, (float4*)hist);

    dim3 grid(WW / 16, HH / 8, BB);
    for (int tstep = 1; tstep <= STEPS; tstep++) {
        nca_step_kernel<<<grid, NT, SMEM_BYTES>>>(
            hist + (size_t)(tstep - 1) * NELEM,
            hist + (size_t)tstep * NELEM,
            b_first, b_interim);
    }

    // x_final = history[STEPS]
    copy_f4_kernel<<<NELEM / 4 / 256, 256>>>(
        (const float4*)(hist + (size_t)STEPS * NELEM), (float4*)out);
}